// round 6
// baseline (speedup 1.0000x reference)
#include <cuda_runtime.h>
#include <cuda_bf16.h>
#include <cstdint>
#include <cstddef>

#define K_CB   2048
#define D_DIM  512
#define B_DIM  16
#define N_DIM  8192
#define M_ROWS (B_DIM * N_DIM)
#define MARGIN 2.0e-3f

// -------- device scratch: separate hi/lo bf16 planes, packed in dim-pairs ----
__device__ uint32_t g_Ah[(size_t)M_ROWS * 256];
__device__ uint32_t g_Al[(size_t)M_ROWS * 256];
__device__ uint32_t g_Bh[(size_t)K_CB * 256];
__device__ uint32_t g_Bl[(size_t)K_CB * 256];
__device__ float    g_e2[K_CB];
__device__ int      g_ind[M_ROWS];
__device__ int      g_lightm[M_ROWS];
__device__ int      g_cand[(size_t)M_ROWS * 4];
__device__ int      g_fullm[M_ROWS];
__device__ int      g_nlight;
__device__ int      g_nfull;

// -------- helpers --------
__device__ __forceinline__ uint32_t smem_u32(const void* p) {
    uint32_t a;
    asm("{ .reg .u64 t; cvta.to.shared.u64 t, %1; cvt.u32.u64 %0, t; }" : "=r"(a) : "l"(p));
    return a;
}
#define CP_A16(s, g) \
    asm volatile("cp.async.cg.shared.global [%0], [%1], 16;" :: "r"(s), "l"(g) : "memory")
#define CP_COMMIT() asm volatile("cp.async.commit_group;" ::: "memory")
#define CP_WAIT(n)  asm volatile("cp.async.wait_group %0;" :: "n"(n) : "memory")

__device__ __forceinline__ void ldsm4(uint32_t* r, uint32_t addr) {
    asm volatile("ldmatrix.sync.aligned.m8n8.x4.shared.b16 {%0,%1,%2,%3}, [%4];"
                 : "=r"(r[0]), "=r"(r[1]), "=r"(r[2]), "=r"(r[3]) : "r"(addr));
}
__device__ __forceinline__ void mma16816(float* c, const uint32_t* a, const uint32_t* b) {
    asm volatile("mma.sync.aligned.m16n8k16.row.col.f32.bf16.bf16.f32 "
                 "{%0,%1,%2,%3}, {%4,%5,%6,%7}, {%8,%9}, {%0,%1,%2,%3};"
                 : "+f"(c[0]), "+f"(c[1]), "+f"(c[2]), "+f"(c[3])
                 : "r"(a[0]), "r"(a[1]), "r"(a[2]), "r"(a[3]), "r"(b[0]), "r"(b[1]));
}
__device__ __forceinline__ uint32_t bf16hi(float v) {
    return (uint32_t)__bfloat16_as_ushort(__float2bfloat16(v));
}
__device__ __forceinline__ uint32_t bf16lo(float v) {
    float hf = __bfloat162float(__float2bfloat16(v));
    return (uint32_t)__bfloat16_as_ushort(__float2bfloat16(v - hf));
}

// -------- prep: codebook hi/lo planes + e2 --------
__global__ __launch_bounds__(128) void prep_embed_kernel(const float* __restrict__ embed) {
    int k = blockIdx.x;
    const float* row = embed + (size_t)k * D_DIM;
    uint32_t* bh = g_Bh + (size_t)k * 256;
    uint32_t* bl = g_Bl + (size_t)k * 256;
    float s = 0.f;
    for (int j = threadIdx.x; j < 256; j += 128) {
        float v0 = row[2 * j], v1 = row[2 * j + 1];
        s += v0 * v0 + v1 * v1;
        bh[j] = bf16hi(v0) | (bf16hi(v1) << 16);
        bl[j] = bf16lo(v0) | (bf16lo(v1) << 16);
    }
    #pragma unroll
    for (int o = 16; o > 0; o >>= 1) s += __shfl_down_sync(0xffffffffu, s, o);
    __shared__ float ws[4];
    if ((threadIdx.x & 31) == 0) ws[threadIdx.x >> 5] = s;
    __syncthreads();
    if (threadIdx.x == 0) g_e2[k] = ws[0] + ws[1] + ws[2] + ws[3];
    if (blockIdx.x == 0 && threadIdx.x == 0) { g_nlight = 0; g_nfull = 0; }
}

// -------- prep: x[B,D,N] -> row-major hi/lo planes --------
__global__ __launch_bounds__(256) void prep_x_kernel(const float* __restrict__ x) {
    __shared__ uint32_t t[64][65];
    int b = blockIdx.y, n0 = blockIdx.x * 64;
    const float* xb = x + (size_t)b * D_DIM * N_DIM + n0;
    for (int dc = 0; dc < 8; dc++) {
        __syncthreads();
        #pragma unroll
        for (int l = 0; l < 16; l++) {
            int i = threadIdx.x + l * 256;
            int dd = i >> 6, nn = i & 63;
            float v = xb[(size_t)(dc * 64 + dd) * N_DIM + nn];
            t[dd][nn] = bf16hi(v) | (bf16lo(v) << 16);
        }
        __syncthreads();
        #pragma unroll
        for (int l = 0; l < 8; l++) {
            int i = threadIdx.x + l * 256;
            int nn = i >> 5, jj = i & 31;
            uint32_t p0 = t[2 * jj][nn], p1 = t[2 * jj + 1][nn];
            size_t o = (size_t)(b * N_DIM + n0 + nn) * 256 + dc * 32 + jj;
            g_Ah[o] = (p0 & 0xffffu) | (p1 << 16);
            g_Al[o] = (p0 >> 16) | (p1 & 0xffff0000u);
        }
    }
}

// -------- tile loader --------
#define STAGE_BYTES 65536
__device__ __forceinline__ void load_tiles(uint32_t ss, const uint4* Ah, const uint4* Al,
                                           const uint4* Bh, const uint4* Bl, int kb, int tid) {
    #pragma unroll
    for (int l = 0; l < 4; l++) {
        int i = tid + l * 256;
        int row = i >> 3, ch = i & 7;
        uint32_t soff = (uint32_t)row * 128 + (uint32_t)((ch ^ (row & 7)) << 4);
        size_t goff = (size_t)row * 64 + (size_t)kb * 8 + ch;
        CP_A16(ss + soff,         Ah + goff);
        CP_A16(ss + 16384 + soff, Al + goff);
        CP_A16(ss + 32768 + soff, Bh + goff);
        CP_A16(ss + 49152 + soff, Bl + goff);
    }
}

// -------- warp-tile compute: 3 bf16 products --------
__device__ __forceinline__ void compute_stage(uint32_t ss, int lane, int wm, int wn,
                                              float acc[2][8][4]) {
    uint32_t sAh = ss, sAl = ss + 16384, sBh = ss + 32768, sBl = ss + 49152;
    #pragma unroll
    for (int kk = 0; kk < 4; kk++) {
        uint32_t ah[2][4], al[2][4];
        #pragma unroll
        for (int i = 0; i < 2; i++) {
            int r = wm * 32 + i * 16 + (lane & 15);
            int c = (kk * 2 + (lane >> 4)) ^ (r & 7);
            ldsm4(ah[i], sAh + r * 128 + c * 16);
            ldsm4(al[i], sAl + r * 128 + c * 16);
        }
        #pragma unroll
        for (int j16 = 0; j16 < 4; j16++) {
            int n = wn * 64 + j16 * 16 + (lane & 7) + ((lane >> 4) << 3);
            int c = (kk * 2 + ((lane >> 3) & 1)) ^ (n & 7);
            uint32_t bh[4], bl[4];
            ldsm4(bh, sBh + n * 128 + c * 16);
            ldsm4(bl, sBl + n * 128 + c * 16);
            #pragma unroll
            for (int i = 0; i < 2; i++) {
                mma16816(acc[i][j16 * 2 + 0], ah[i], bh + 0);
                mma16816(acc[i][j16 * 2 + 1], ah[i], bh + 2);
                mma16816(acc[i][j16 * 2 + 0], al[i], bh + 0);
                mma16816(acc[i][j16 * 2 + 1], al[i], bh + 2);
                mma16816(acc[i][j16 * 2 + 0], ah[i], bl + 0);
                mma16816(acc[i][j16 * 2 + 1], ah[i], bl + 2);
            }
        }
    }
}

#define INS3(r, s, k) do {                                                        \
    if ((s) > v1[r]) { v3[r] = v2[r]; v2[r] = v1[r]; i2[r] = i1[r];               \
                       v1[r] = (s); i1[r] = (k); }                                \
    else if ((s) > v2[r]) { v3[r] = v2[r]; v2[r] = (s); i2[r] = (k); }            \
    else if ((s) > v3[r]) { v3[r] = (s); }                                        \
} while (0)

// -------- main dist + argmax/classify kernel --------
__global__ void __launch_bounds__(256) vq_dist_kernel(float* __restrict__ out_ind_f) {
    extern __shared__ char smem[];
    uint32_t sb = smem_u32(smem);
    const int tid = threadIdx.x, lane = tid & 31, wid = tid >> 5;
    const int wm = wid & 3, wn = wid >> 2;
    const int m0 = blockIdx.x * 128;
    const uint4* Ah = (const uint4*)(g_Ah + (size_t)m0 * 256);
    const uint4* Al = (const uint4*)(g_Al + (size_t)m0 * 256);

    float v1[4], v2[4], v3[4];
    int   i1[4], i2[4];
    #pragma unroll
    for (int r = 0; r < 4; r++) {
        v1[r] = v2[r] = v3[r] = -3.0e38f;
        i1[r] = i2[r] = 0;
    }

    for (int nt = 0; nt < 16; nt++) {
        const uint4* Bh = (const uint4*)(g_Bh + (size_t)nt * 128 * 256);
        const uint4* Bl = (const uint4*)(g_Bl + (size_t)nt * 128 * 256);

        float acc[2][8][4];
        #pragma unroll
        for (int i = 0; i < 2; i++)
            #pragma unroll
            for (int j = 0; j < 8; j++)
                #pragma unroll
                for (int q = 0; q < 4; q++) acc[i][j][q] = 0.f;

        load_tiles(sb, Ah, Al, Bh, Bl, 0, tid);
        CP_COMMIT();
        for (int kb = 0; kb < 8; kb++) {
            uint32_t cur = sb + (kb & 1) * STAGE_BYTES;
            if (kb < 7) {
                load_tiles(sb + ((kb + 1) & 1) * STAGE_BYTES, Ah, Al, Bh, Bl, kb + 1, tid);
                CP_COMMIT();
                CP_WAIT(1);
            } else {
                CP_WAIT(0);
            }
            __syncthreads();
            compute_stage(cur, lane, wm, wn, acc);
            __syncthreads();
        }

        #pragma unroll
        for (int j = 0; j < 8; j++) {
            int kb_ = nt * 128 + wn * 64 + j * 8 + (lane & 3) * 2;
            float e2a = g_e2[kb_], e2b = g_e2[kb_ + 1];
            #pragma unroll
            for (int i = 0; i < 2; i++) {
                float s0 = 2.f * acc[i][j][0] - e2a;
                float s1 = 2.f * acc[i][j][1] - e2b;
                float s2 = 2.f * acc[i][j][2] - e2a;
                float s3 = 2.f * acc[i][j][3] - e2b;
                int r0 = i * 2, r1 = i * 2 + 1;
                INS3(r0, s0, kb_);
                INS3(r0, s1, kb_ + 1);
                INS3(r1, s2, kb_);
                INS3(r1, s3, kb_ + 1);
            }
        }
    }

    // ---- per-row merge over 8 sources, classify row ----
    // reuse dynamic smem: per (row, src): 3 floats + 2 ints
    float* sV = (float*)smem;                 // [128][8][3]
    int*   sI = (int*)(smem + 128 * 8 * 3 * 4); // [128][8][2]
    __syncthreads();
    #pragma unroll
    for (int r = 0; r < 4; r++) {
        int row = wm * 32 + (r >> 1) * 16 + (r & 1) * 8 + (lane >> 2);
        int src = wn * 4 + (lane & 3);
        float* v = sV + (row * 8 + src) * 3;
        v[0] = v1[r]; v[1] = v2[r]; v[2] = v3[r];
        int* ii = sI + (row * 8 + src) * 2;
        ii[0] = i1[r]; ii[1] = i2[r];
    }
    __syncthreads();
    if (tid < 128) {
        float b1 = -3.0e38f; int bi1 = 0x7fffffff;
        #pragma unroll
        for (int s = 0; s < 8; s++) {
            float v = sV[(tid * 8 + s) * 3];
            int   i = sI[(tid * 8 + s) * 2];
            if (v > b1 || (v == b1 && i < bi1)) { b1 = v; bi1 = i; }
        }
        float thr = b1 - MARGIN;
        int cand[4]; int nc = 0; bool overflow = false;
        #pragma unroll
        for (int s = 0; s < 8; s++) {
            float va = sV[(tid * 8 + s) * 3 + 0];
            float vb = sV[(tid * 8 + s) * 3 + 1];
            float vc = sV[(tid * 8 + s) * 3 + 2];
            int ia = sI[(tid * 8 + s) * 2 + 0];
            int ib = sI[(tid * 8 + s) * 2 + 1];
            if (va >= thr) { if (nc < 4) cand[nc] = ia; nc++; }
            if (vb >= thr) { if (nc < 4) cand[nc] = ib; nc++; }
            if (vc >= thr) overflow = true;
        }
        int m = m0 + tid;
        if (!overflow && nc <= 1) {
            g_ind[m] = bi1;
            out_ind_f[m] = (float)bi1;
        } else if (!overflow && nc <= 4) {
            int slot = atomicAdd(&g_nlight, 1);
            g_lightm[slot] = m;
            #pragma unroll
            for (int c = 0; c < 4; c++) g_cand[(size_t)slot * 4 + c] = (c < nc) ? cand[c] : -1;
        } else {
            int slot = atomicAdd(&g_nfull, 1);
            g_fullm[slot] = m;
        }
    }
}

// -------- light fallback: exact rescore of <=4 candidates, 1 thread/row -----
__global__ __launch_bounds__(256) void light_kernel(const float* __restrict__ x,
                                                    const float* __restrict__ embed,
                                                    float* __restrict__ out_ind_f) {
    int nl = g_nlight;
    for (int s = blockIdx.x * 256 + threadIdx.x; s < nl; s += gridDim.x * 256) {
        int m = g_lightm[s];
        int b = m >> 13, n = m & (N_DIM - 1);
        const float* xb = x + (size_t)b * D_DIM * N_DIM + n;
        int k0 = g_cand[(size_t)s * 4 + 0];
        int k1 = g_cand[(size_t)s * 4 + 1];
        int k2 = g_cand[(size_t)s * 4 + 2];
        int k3 = g_cand[(size_t)s * 4 + 3];
        const float* e0 = embed + (size_t)max(k0, 0) * D_DIM;
        const float* e1 = embed + (size_t)max(k1, 0) * D_DIM;
        const float* e2p = embed + (size_t)max(k2, 0) * D_DIM;
        const float* e3 = embed + (size_t)max(k3, 0) * D_DIM;
        float a0 = 0.f, a1 = 0.f, a2 = 0.f, a3 = 0.f;
        #pragma unroll 4
        for (int d = 0; d < D_DIM; d++) {
            float xv = xb[(size_t)d * N_DIM];
            a0 += xv * e0[d];
            a1 += xv * e1[d];
            a2 += xv * e2p[d];
            a3 += xv * e3[d];
        }
        float best = -3.0e38f; int bi = 0x7fffffff;
        float sc;
        sc = 2.f * a0 - g_e2[max(k0, 0)];
        if (k0 >= 0 && (sc > best || (sc == best && k0 < bi))) { best = sc; bi = k0; }
        sc = 2.f * a1 - g_e2[max(k1, 0)];
        if (k1 >= 0 && (sc > best || (sc == best && k1 < bi))) { best = sc; bi = k1; }
        sc = 2.f * a2 - g_e2[max(k2, 0)];
        if (k2 >= 0 && (sc > best || (sc == best && k2 < bi))) { best = sc; bi = k2; }
        sc = 2.f * a3 - g_e2[max(k3, 0)];
        if (k3 >= 0 && (sc > best || (sc == best && k3 < bi))) { best = sc; bi = k3; }
        g_ind[m] = bi;
        out_ind_f[m] = (float)bi;
    }
}

// -------- full fallback: exact scan of all codewords (rare) --------
__global__ __launch_bounds__(256) void full_kernel(const float* __restrict__ x,
                                                   const float* __restrict__ embed,
                                                   float* __restrict__ out_ind_f) {
    __shared__ float xr[D_DIM];
    __shared__ float bv[256];
    __shared__ int   bI[256];
    int nf = g_nfull;
    for (int f = blockIdx.x; f < nf; f += gridDim.x) {
        int m = g_fullm[f];
        int b = m >> 13, n = m & (N_DIM - 1);
        __syncthreads();
        for (int d = threadIdx.x; d < D_DIM; d += 256)
            xr[d] = x[(size_t)b * D_DIM * N_DIM + (size_t)d * N_DIM + n];
        __syncthreads();
        float best = -3.0e38f; int bi = 0x7fffffff;
        for (int c = 0; c < 8; c++) {
            int k = threadIdx.x + c * 256;
            const float4* er = (const float4*)(embed + (size_t)k * D_DIM);
            float s0 = 0.f, s1 = 0.f, s2 = 0.f, s3 = 0.f;
            #pragma unroll 8
            for (int j = 0; j < 128; j++) {
                float4 e = er[j];
                s0 += xr[4 * j + 0] * e.x;
                s1 += xr[4 * j + 1] * e.y;
                s2 += xr[4 * j + 2] * e.z;
                s3 += xr[4 * j + 3] * e.w;
            }
            float sc = 2.f * ((s0 + s1) + (s2 + s3)) - g_e2[k];
            if (sc > best || (sc == best && k < bi)) { best = sc; bi = k; }
        }
        bv[threadIdx.x] = best; bI[threadIdx.x] = bi;
        __syncthreads();
        for (int o = 128; o > 0; o >>= 1) {
            if (threadIdx.x < o) {
                float ov = bv[threadIdx.x + o]; int oi = bI[threadIdx.x + o];
                if (ov > bv[threadIdx.x] || (ov == bv[threadIdx.x] && oi < bI[threadIdx.x])) {
                    bv[threadIdx.x] = ov; bI[threadIdx.x] = oi;
                }
            }
            __syncthreads();
        }
        if (threadIdx.x == 0) { g_ind[m] = bI[0]; out_ind_f[m] = (float)bI[0]; }
    }
}

// -------- gather: out[b,d,n] = embed[ind[b,n], d] --------
__global__ __launch_bounds__(256) void gather_kernel(const float* __restrict__ embed,
                                                     float* __restrict__ out) {
    extern __shared__ float tile[];
    __shared__ int inds[32];
    const int bb = blockIdx.y;
    const int n0 = blockIdx.x * 32;
    if (threadIdx.x < 32) inds[threadIdx.x] = g_ind[bb * N_DIM + n0 + threadIdx.x];
    __syncthreads();
    for (int i = threadIdx.x; i < 32 * D_DIM; i += 256) {
        int n = i >> 9, d = i & (D_DIM - 1);
        tile[n * 513 + d] = embed[(size_t)inds[n] * D_DIM + d];
    }
    __syncthreads();
    float* obase = out + (size_t)bb * D_DIM * N_DIM + n0;
    for (int i = threadIdx.x; i < 32 * D_DIM; i += 256) {
        int n = i & 31, d = i >> 5;
        obase[(size_t)d * N_DIM + n] = tile[n * 513 + d];
    }
}

// ---------------------------------------------------------------------------
extern "C" void kernel_launch(void* const* d_in, const int* in_sizes, int n_in,
                              void* d_out, int out_size) {
    const float* x     = (const float*)d_in[0];
    const float* embed = (const float*)d_in[1];
    float* out   = (float*)d_out;
    float* out_q = out;
    float* out_i = out + (size_t)B_DIM * D_DIM * N_DIM;
    (void)in_sizes; (void)n_in; (void)out_size;

    static const int gather_smem = 32 * 513 * (int)sizeof(float);
    static const int dist_smem = 2 * STAGE_BYTES;   // 128 KB
    cudaFuncSetAttribute(gather_kernel, cudaFuncAttributeMaxDynamicSharedMemorySize, gather_smem);
    cudaFuncSetAttribute(vq_dist_kernel, cudaFuncAttributeMaxDynamicSharedMemorySize, dist_smem);

    prep_embed_kernel<<<K_CB, 128>>>(embed);
    prep_x_kernel<<<dim3(N_DIM / 64, B_DIM), 256>>>(x);
    vq_dist_kernel<<<M_ROWS / 128, 256, dist_smem>>>(out_i);
    light_kernel<<<256, 256>>>(x, embed, out_i);
    full_kernel<<<128, 256>>>(x, embed, out_i);
    gather_kernel<<<dim3(N_DIM / 32, B_DIM), 256, gather_smem>>>(embed, out_q);
}

// round 7
// speedup vs baseline: 1.0675x; 1.0675x over previous
#include <cuda_runtime.h>
#include <cuda_bf16.h>
#include <cstdint>
#include <cstddef>

#define K_CB   2048
#define D_DIM  512
#define B_DIM  16
#define N_DIM  8192
#define M_ROWS (B_DIM * N_DIM)
#define MARGIN 2.0e-3f

// -------- device scratch: separate hi/lo bf16 planes, packed in dim-pairs ----
__device__ uint32_t g_Ah[(size_t)M_ROWS * 256];
__device__ uint32_t g_Al[(size_t)M_ROWS * 256];
__device__ uint32_t g_Bh[(size_t)K_CB * 256];
__device__ uint32_t g_Bl[(size_t)K_CB * 256];
__device__ float    g_e2[K_CB];
__device__ int      g_ind[M_ROWS];
__device__ int      g_lightm[M_ROWS];
__device__ int      g_cand[(size_t)M_ROWS * 4];
__device__ int      g_fullm[M_ROWS];
__device__ int      g_nlight;
__device__ int      g_nfull;

// -------- helpers --------
__device__ __forceinline__ uint32_t smem_u32(const void* p) {
    uint32_t a;
    asm("{ .reg .u64 t; cvta.to.shared.u64 t, %1; cvt.u32.u64 %0, t; }" : "=r"(a) : "l"(p));
    return a;
}
#define CP_A16(s, g) \
    asm volatile("cp.async.cg.shared.global [%0], [%1], 16;" :: "r"(s), "l"(g) : "memory")
#define CP_COMMIT() asm volatile("cp.async.commit_group;" ::: "memory")
#define CP_WAIT(n)  asm volatile("cp.async.wait_group %0;" :: "n"(n) : "memory")

__device__ __forceinline__ void ldsm4(uint32_t* r, uint32_t addr) {
    asm volatile("ldmatrix.sync.aligned.m8n8.x4.shared.b16 {%0,%1,%2,%3}, [%4];"
                 : "=r"(r[0]), "=r"(r[1]), "=r"(r[2]), "=r"(r[3]) : "r"(addr));
}
__device__ __forceinline__ void mma16816(float* c, const uint32_t* a, const uint32_t* b) {
    asm volatile("mma.sync.aligned.m16n8k16.row.col.f32.bf16.bf16.f32 "
                 "{%0,%1,%2,%3}, {%4,%5,%6,%7}, {%8,%9}, {%0,%1,%2,%3};"
                 : "+f"(c[0]), "+f"(c[1]), "+f"(c[2]), "+f"(c[3])
                 : "r"(a[0]), "r"(a[1]), "r"(a[2]), "r"(a[3]), "r"(b[0]), "r"(b[1]));
}
__device__ __forceinline__ uint32_t bf16hi(float v) {
    return (uint32_t)__bfloat16_as_ushort(__float2bfloat16(v));
}
__device__ __forceinline__ uint32_t bf16lo(float v) {
    float hf = __bfloat162float(__float2bfloat16(v));
    return (uint32_t)__bfloat16_as_ushort(__float2bfloat16(v - hf));
}

// -------- prep: codebook hi/lo planes + e2 --------
__global__ __launch_bounds__(128) void prep_embed_kernel(const float* __restrict__ embed) {
    int k = blockIdx.x;
    const float* row = embed + (size_t)k * D_DIM;
    uint32_t* bh = g_Bh + (size_t)k * 256;
    uint32_t* bl = g_Bl + (size_t)k * 256;
    float s = 0.f;
    for (int j = threadIdx.x; j < 256; j += 128) {
        float v0 = row[2 * j], v1 = row[2 * j + 1];
        s += v0 * v0 + v1 * v1;
        bh[j] = bf16hi(v0) | (bf16hi(v1) << 16);
        bl[j] = bf16lo(v0) | (bf16lo(v1) << 16);
    }
    #pragma unroll
    for (int o = 16; o > 0; o >>= 1) s += __shfl_down_sync(0xffffffffu, s, o);
    __shared__ float ws[4];
    if ((threadIdx.x & 31) == 0) ws[threadIdx.x >> 5] = s;
    __syncthreads();
    if (threadIdx.x == 0) g_e2[k] = ws[0] + ws[1] + ws[2] + ws[3];
    if (blockIdx.x == 0 && threadIdx.x == 0) { g_nlight = 0; g_nfull = 0; }
}

// -------- prep: x[B,D,N] -> row-major hi/lo planes --------
__global__ __launch_bounds__(256) void prep_x_kernel(const float* __restrict__ x) {
    __shared__ uint32_t t[64][65];
    int b = blockIdx.y, n0 = blockIdx.x * 64;
    const float* xb = x + (size_t)b * D_DIM * N_DIM + n0;
    for (int dc = 0; dc < 8; dc++) {
        __syncthreads();
        #pragma unroll
        for (int l = 0; l < 16; l++) {
            int i = threadIdx.x + l * 256;
            int dd = i >> 6, nn = i & 63;
            float v = xb[(size_t)(dc * 64 + dd) * N_DIM + nn];
            t[dd][nn] = bf16hi(v) | (bf16lo(v) << 16);
        }
        __syncthreads();
        #pragma unroll
        for (int l = 0; l < 8; l++) {
            int i = threadIdx.x + l * 256;
            int nn = i >> 5, jj = i & 31;
            uint32_t p0 = t[2 * jj][nn], p1 = t[2 * jj + 1][nn];
            size_t o = (size_t)(b * N_DIM + n0 + nn) * 256 + dc * 32 + jj;
            g_Ah[o] = (p0 & 0xffffu) | (p1 << 16);
            g_Al[o] = (p0 >> 16) | (p1 & 0xffff0000u);
        }
    }
}

// -------- tile loader --------
#define STAGE_BYTES 65536
__device__ __forceinline__ void load_tiles(uint32_t ss, const uint4* Ah, const uint4* Al,
                                           const uint4* Bh, const uint4* Bl, int kb, int tid) {
    #pragma unroll
    for (int l = 0; l < 4; l++) {
        int i = tid + l * 256;
        int row = i >> 3, ch = i & 7;
        uint32_t soff = (uint32_t)row * 128 + (uint32_t)((ch ^ (row & 7)) << 4);
        size_t goff = (size_t)row * 64 + (size_t)kb * 8 + ch;
        CP_A16(ss + soff,         Ah + goff);
        CP_A16(ss + 16384 + soff, Al + goff);
        CP_A16(ss + 32768 + soff, Bh + goff);
        CP_A16(ss + 49152 + soff, Bl + goff);
    }
}

// -------- warp-tile compute: 3 bf16 products --------
__device__ __forceinline__ void compute_stage(uint32_t ss, int lane, int wm, int wn,
                                              float acc[2][8][4]) {
    uint32_t sAh = ss, sAl = ss + 16384, sBh = ss + 32768, sBl = ss + 49152;
    #pragma unroll
    for (int kk = 0; kk < 4; kk++) {
        uint32_t ah[2][4], al[2][4];
        #pragma unroll
        for (int i = 0; i < 2; i++) {
            int r = wm * 32 + i * 16 + (lane & 15);
            int c = (kk * 2 + (lane >> 4)) ^ (r & 7);
            ldsm4(ah[i], sAh + r * 128 + c * 16);
            ldsm4(al[i], sAl + r * 128 + c * 16);
        }
        #pragma unroll
        for (int j16 = 0; j16 < 4; j16++) {
            int n = wn * 64 + j16 * 16 + (lane & 7) + ((lane >> 4) << 3);
            int c = (kk * 2 + ((lane >> 3) & 1)) ^ (n & 7);
            uint32_t bh[4], bl[4];
            ldsm4(bh, sBh + n * 128 + c * 16);
            ldsm4(bl, sBl + n * 128 + c * 16);
            #pragma unroll
            for (int i = 0; i < 2; i++) {
                mma16816(acc[i][j16 * 2 + 0], ah[i], bh + 0);
                mma16816(acc[i][j16 * 2 + 1], ah[i], bh + 2);
                mma16816(acc[i][j16 * 2 + 0], al[i], bh + 0);
                mma16816(acc[i][j16 * 2 + 1], al[i], bh + 2);
                mma16816(acc[i][j16 * 2 + 0], ah[i], bl + 0);
                mma16816(acc[i][j16 * 2 + 1], ah[i], bl + 2);
            }
        }
    }
}

#define INS3(r, s, k) do {                                                        \
    if ((s) > v1[r]) { v3[r] = v2[r]; v2[r] = v1[r]; i2[r] = i1[r];               \
                       v1[r] = (s); i1[r] = (k); }                                \
    else if ((s) > v2[r]) { v3[r] = v2[r]; v2[r] = (s); i2[r] = (k); }            \
    else if ((s) > v3[r]) { v3[r] = (s); }                                        \
} while (0)

// -------- main dist + argmax/classify kernel --------
__global__ void __launch_bounds__(256) vq_dist_kernel(float* __restrict__ out_ind_f) {
    extern __shared__ char smem[];
    uint32_t sb = smem_u32(smem);
    const int tid = threadIdx.x, lane = tid & 31, wid = tid >> 5;
    const int wm = wid & 3, wn = wid >> 2;
    const int m0 = blockIdx.x * 128;
    const uint4* Ah = (const uint4*)(g_Ah + (size_t)m0 * 256);
    const uint4* Al = (const uint4*)(g_Al + (size_t)m0 * 256);

    float v1[4], v2[4], v3[4];
    int   i1[4], i2[4];
    #pragma unroll
    for (int r = 0; r < 4; r++) {
        v1[r] = v2[r] = v3[r] = -3.0e38f;
        i1[r] = i2[r] = 0;
    }

    for (int nt = 0; nt < 16; nt++) {
        const uint4* Bh = (const uint4*)(g_Bh + (size_t)nt * 128 * 256);
        const uint4* Bl = (const uint4*)(g_Bl + (size_t)nt * 128 * 256);

        float acc[2][8][4];
        #pragma unroll
        for (int i = 0; i < 2; i++)
            #pragma unroll
            for (int j = 0; j < 8; j++)
                #pragma unroll
                for (int q = 0; q < 4; q++) acc[i][j][q] = 0.f;

        load_tiles(sb, Ah, Al, Bh, Bl, 0, tid);
        CP_COMMIT();
        for (int kb = 0; kb < 8; kb++) {
            uint32_t cur = sb + (kb & 1) * STAGE_BYTES;
            if (kb < 7) {
                load_tiles(sb + ((kb + 1) & 1) * STAGE_BYTES, Ah, Al, Bh, Bl, kb + 1, tid);
                CP_COMMIT();
                CP_WAIT(1);
            } else {
                CP_WAIT(0);
            }
            __syncthreads();
            compute_stage(cur, lane, wm, wn, acc);
            __syncthreads();
        }

        #pragma unroll
        for (int j = 0; j < 8; j++) {
            int kb_ = nt * 128 + wn * 64 + j * 8 + (lane & 3) * 2;
            float e2a = g_e2[kb_], e2b = g_e2[kb_ + 1];
            #pragma unroll
            for (int i = 0; i < 2; i++) {
                float s0 = 2.f * acc[i][j][0] - e2a;
                float s1 = 2.f * acc[i][j][1] - e2b;
                float s2 = 2.f * acc[i][j][2] - e2a;
                float s3 = 2.f * acc[i][j][3] - e2b;
                int r0 = i * 2, r1 = i * 2 + 1;
                INS3(r0, s0, kb_);
                INS3(r0, s1, kb_ + 1);
                INS3(r1, s2, kb_);
                INS3(r1, s3, kb_ + 1);
            }
        }
    }

    // ---- per-row merge over 8 sources, classify row ----
    float* sV = (float*)smem;                   // [128][8][3]
    int*   sI = (int*)(smem + 128 * 8 * 3 * 4); // [128][8][2]
    __syncthreads();
    #pragma unroll
    for (int r = 0; r < 4; r++) {
        int row = wm * 32 + (r >> 1) * 16 + (r & 1) * 8 + (lane >> 2);
        int src = wn * 4 + (lane & 3);
        float* v = sV + (row * 8 + src) * 3;
        v[0] = v1[r]; v[1] = v2[r]; v[2] = v3[r];
        int* ii = sI + (row * 8 + src) * 2;
        ii[0] = i1[r]; ii[1] = i2[r];
    }
    __syncthreads();
    if (tid < 128) {
        float b1 = -3.0e38f; int bi1 = 0x7fffffff;
        #pragma unroll
        for (int s = 0; s < 8; s++) {
            float v = sV[(tid * 8 + s) * 3];
            int   i = sI[(tid * 8 + s) * 2];
            if (v > b1 || (v == b1 && i < bi1)) { b1 = v; bi1 = i; }
        }
        float thr = b1 - MARGIN;
        int cand[4]; int nc = 0; bool overflow = false;
        #pragma unroll
        for (int s = 0; s < 8; s++) {
            float va = sV[(tid * 8 + s) * 3 + 0];
            float vb = sV[(tid * 8 + s) * 3 + 1];
            float vc = sV[(tid * 8 + s) * 3 + 2];
            int ia = sI[(tid * 8 + s) * 2 + 0];
            int ib = sI[(tid * 8 + s) * 2 + 1];
            if (va >= thr) { if (nc < 4) cand[nc] = ia; nc++; }
            if (vb >= thr) { if (nc < 4) cand[nc] = ib; nc++; }
            if (vc >= thr) overflow = true;
        }
        int m = m0 + tid;
        if (!overflow && nc <= 1) {
            g_ind[m] = bi1;
            out_ind_f[m] = (float)bi1;
        } else if (!overflow && nc <= 4) {
            int slot = atomicAdd(&g_nlight, 1);
            g_lightm[slot] = m;
            #pragma unroll
            for (int c = 0; c < 4; c++) g_cand[(size_t)slot * 4 + c] = (c < nc) ? cand[c] : -1;
        } else {
            int slot = atomicAdd(&g_nfull, 1);
            g_fullm[slot] = m;
        }
    }
}

// -------- light fallback: exact rescore of <=4 candidates, WARP per row -----
__global__ __launch_bounds__(256) void light_kernel(const float* __restrict__ x,
                                                    const float* __restrict__ embed,
                                                    float* __restrict__ out_ind_f) {
    const int nl = g_nlight;
    const int lane = threadIdx.x & 31;
    const int wglob = blockIdx.x * 8 + (threadIdx.x >> 5);
    for (int s = wglob; s < nl; s += gridDim.x * 8) {
        int m = g_lightm[s];
        int b = m >> 13, n = m & (N_DIM - 1);
        const float* xb = x + (size_t)b * D_DIM * N_DIM + n;
        // load this row's x once: lane handles dims lane, lane+32, ...
        float xr[16];
        #pragma unroll
        for (int j = 0; j < 16; j++)
            xr[j] = xb[(size_t)(lane + 32 * j) * N_DIM];
        float best = -3.0e38f; int bi = 0x7fffffff;
        #pragma unroll
        for (int c = 0; c < 4; c++) {
            int k = g_cand[(size_t)s * 4 + c];
            if (k < 0) break;                       // uniform across warp
            const float* e = embed + (size_t)k * D_DIM;
            float a = 0.f;
            #pragma unroll
            for (int j = 0; j < 16; j++)
                a += xr[j] * e[lane + 32 * j];      // coalesced across lanes
            #pragma unroll
            for (int o = 16; o > 0; o >>= 1)
                a += __shfl_xor_sync(0xffffffffu, a, o);
            float sc = 2.f * a - g_e2[k];
            if (sc > best || (sc == best && k < bi)) { best = sc; bi = k; }
        }
        if (lane == 0) { g_ind[m] = bi; out_ind_f[m] = (float)bi; }
    }
}

// -------- full fallback: exact scan of all codewords (rare) --------
__global__ __launch_bounds__(256) void full_kernel(const float* __restrict__ x,
                                                   const float* __restrict__ embed,
                                                   float* __restrict__ out_ind_f) {
    __shared__ float xr[D_DIM];
    __shared__ float bv[256];
    __shared__ int   bI[256];
    int nf = g_nfull;
    for (int f = blockIdx.x; f < nf; f += gridDim.x) {
        int m = g_fullm[f];
        int b = m >> 13, n = m & (N_DIM - 1);
        __syncthreads();
        for (int d = threadIdx.x; d < D_DIM; d += 256)
            xr[d] = x[(size_t)b * D_DIM * N_DIM + (size_t)d * N_DIM + n];
        __syncthreads();
        float best = -3.0e38f; int bi = 0x7fffffff;
        for (int c = 0; c < 8; c++) {
            int k = threadIdx.x + c * 256;
            const float4* er = (const float4*)(embed + (size_t)k * D_DIM);
            float s0 = 0.f, s1 = 0.f, s2 = 0.f, s3 = 0.f;
            #pragma unroll 8
            for (int j = 0; j < 128; j++) {
                float4 e = er[j];
                s0 += xr[4 * j + 0] * e.x;
                s1 += xr[4 * j + 1] * e.y;
                s2 += xr[4 * j + 2] * e.z;
                s3 += xr[4 * j + 3] * e.w;
            }
            float sc = 2.f * ((s0 + s1) + (s2 + s3)) - g_e2[k];
            if (sc > best || (sc == best && k < bi)) { best = sc; bi = k; }
        }
        bv[threadIdx.x] = best; bI[threadIdx.x] = bi;
        __syncthreads();
        for (int o = 128; o > 0; o >>= 1) {
            if (threadIdx.x < o) {
                float ov = bv[threadIdx.x + o]; int oi = bI[threadIdx.x + o];
                if (ov > bv[threadIdx.x] || (ov == bv[threadIdx.x] && oi < bI[threadIdx.x])) {
                    bv[threadIdx.x] = ov; bI[threadIdx.x] = oi;
                }
            }
            __syncthreads();
        }
        if (threadIdx.x == 0) { g_ind[m] = bI[0]; out_ind_f[m] = (float)bI[0]; }
    }
}

// -------- gather: out[b,d,n] = embed[ind[b,n], d] --------
__global__ __launch_bounds__(256) void gather_kernel(const float* __restrict__ embed,
                                                     float* __restrict__ out) {
    extern __shared__ float tile[];
    __shared__ int inds[32];
    const int bb = blockIdx.y;
    const int n0 = blockIdx.x * 32;
    if (threadIdx.x < 32) inds[threadIdx.x] = g_ind[bb * N_DIM + n0 + threadIdx.x];
    __syncthreads();
    for (int i = threadIdx.x; i < 32 * D_DIM; i += 256) {
        int n = i >> 9, d = i & (D_DIM - 1);
        tile[n * 513 + d] = embed[(size_t)inds[n] * D_DIM + d];
    }
    __syncthreads();
    float* obase = out + (size_t)bb * D_DIM * N_DIM + n0;
    for (int i = threadIdx.x; i < 32 * D_DIM; i += 256) {
        int n = i & 31, d = i >> 5;
        obase[(size_t)d * N_DIM + n] = tile[n * 513 + d];
    }
}

// ---------------------------------------------------------------------------
extern "C" void kernel_launch(void* const* d_in, const int* in_sizes, int n_in,
                              void* d_out, int out_size) {
    const float* x     = (const float*)d_in[0];
    const float* embed = (const float*)d_in[1];
    float* out   = (float*)d_out;
    float* out_q = out;
    float* out_i = out + (size_t)B_DIM * D_DIM * N_DIM;
    (void)in_sizes; (void)n_in; (void)out_size;

    static const int gather_smem = 32 * 513 * (int)sizeof(float);
    static const int dist_smem = 2 * STAGE_BYTES;   // 128 KB
    cudaFuncSetAttribute(gather_kernel, cudaFuncAttributeMaxDynamicSharedMemorySize, gather_smem);
    cudaFuncSetAttribute(vq_dist_kernel, cudaFuncAttributeMaxDynamicSharedMemorySize, dist_smem);

    prep_embed_kernel<<<K_CB, 128>>>(embed);
    prep_x_kernel<<<dim3(N_DIM / 64, B_DIM), 256>>>(x);
    vq_dist_kernel<<<M_ROWS / 128, 256, dist_smem>>>(out_i);
    light_kernel<<<1024, 256>>>(x, embed, out_i);
    full_kernel<<<128, 256>>>(x, embed, out_i);
    gather_kernel<<<dim3(N_DIM / 32, B_DIM), 256, gather_smem>>>(embed, out_q);
}

// round 8
// speedup vs baseline: 1.9046x; 1.7842x over previous
#include <cuda_runtime.h>
#include <cuda_bf16.h>
#include <cstdint>
#include <cstddef>

#define K_CB   2048
#define D_DIM  512
#define B_DIM  16
#define N_DIM  8192
#define M_ROWS (B_DIM * N_DIM)
#define MARGIN 1.0f

// -------- device scratch: hi bf16 planes only, packed in dim-pairs ----------
__device__ uint32_t g_Ah[(size_t)M_ROWS * 256];
__device__ uint32_t g_Bh[(size_t)K_CB * 256];
__device__ float    g_e2[K_CB];
__device__ int      g_ind[M_ROWS];
__device__ int      g_lightm[M_ROWS];
__device__ int      g_cand[(size_t)M_ROWS * 4];
__device__ int      g_fullm[M_ROWS];
__device__ int      g_nlight;
__device__ int      g_nfull;

// -------- helpers --------
__device__ __forceinline__ uint32_t smem_u32(const void* p) {
    uint32_t a;
    asm("{ .reg .u64 t; cvta.to.shared.u64 t, %1; cvt.u32.u64 %0, t; }" : "=r"(a) : "l"(p));
    return a;
}
#define CP_A16(s, g) \
    asm volatile("cp.async.cg.shared.global [%0], [%1], 16;" :: "r"(s), "l"(g) : "memory")
#define CP_COMMIT() asm volatile("cp.async.commit_group;" ::: "memory")
#define CP_WAIT(n)  asm volatile("cp.async.wait_group %0;" :: "n"(n) : "memory")

__device__ __forceinline__ void ldsm4(uint32_t* r, uint32_t addr) {
    asm volatile("ldmatrix.sync.aligned.m8n8.x4.shared.b16 {%0,%1,%2,%3}, [%4];"
                 : "=r"(r[0]), "=r"(r[1]), "=r"(r[2]), "=r"(r[3]) : "r"(addr));
}
__device__ __forceinline__ void mma16816(float* c, const uint32_t* a, const uint32_t* b) {
    asm volatile("mma.sync.aligned.m16n8k16.row.col.f32.bf16.bf16.f32 "
                 "{%0,%1,%2,%3}, {%4,%5,%6,%7}, {%8,%9}, {%0,%1,%2,%3};"
                 : "+f"(c[0]), "+f"(c[1]), "+f"(c[2]), "+f"(c[3])
                 : "r"(a[0]), "r"(a[1]), "r"(a[2]), "r"(a[3]), "r"(b[0]), "r"(b[1]));
}
__device__ __forceinline__ uint32_t bf16hi(float v) {
    return (uint32_t)__bfloat16_as_ushort(__float2bfloat16(v));
}

// -------- prep: codebook hi plane + e2 --------
__global__ __launch_bounds__(128) void prep_embed_kernel(const float* __restrict__ embed) {
    int k = blockIdx.x;
    const float* row = embed + (size_t)k * D_DIM;
    uint32_t* bh = g_Bh + (size_t)k * 256;
    float s = 0.f;
    for (int j = threadIdx.x; j < 256; j += 128) {
        float v0 = row[2 * j], v1 = row[2 * j + 1];
        s += v0 * v0 + v1 * v1;
        bh[j] = bf16hi(v0) | (bf16hi(v1) << 16);
    }
    #pragma unroll
    for (int o = 16; o > 0; o >>= 1) s += __shfl_down_sync(0xffffffffu, s, o);
    __shared__ float ws[4];
    if ((threadIdx.x & 31) == 0) ws[threadIdx.x >> 5] = s;
    __syncthreads();
    if (threadIdx.x == 0) g_e2[k] = ws[0] + ws[1] + ws[2] + ws[3];
    if (blockIdx.x == 0 && threadIdx.x == 0) { g_nlight = 0; g_nfull = 0; }
}

// -------- prep: x[B,D,N] -> row-major hi plane (transpose through smem) -----
__global__ __launch_bounds__(256) void prep_x_kernel(const float* __restrict__ x) {
    __shared__ uint16_t t[64][66];
    int b = blockIdx.y, n0 = blockIdx.x * 64;
    const float* xb = x + (size_t)b * D_DIM * N_DIM + n0;
    for (int dc = 0; dc < 8; dc++) {
        __syncthreads();
        #pragma unroll
        for (int l = 0; l < 16; l++) {
            int i = threadIdx.x + l * 256;
            int dd = i >> 6, nn = i & 63;
            t[dd][nn] = (uint16_t)bf16hi(xb[(size_t)(dc * 64 + dd) * N_DIM + nn]);
        }
        __syncthreads();
        #pragma unroll
        for (int l = 0; l < 8; l++) {
            int i = threadIdx.x + l * 256;
            int nn = i >> 5, jj = i & 31;
            uint32_t p = (uint32_t)t[2 * jj][nn] | ((uint32_t)t[2 * jj + 1][nn] << 16);
            g_Ah[(size_t)(b * N_DIM + n0 + nn) * 256 + dc * 32 + jj] = p;
        }
    }
}

// -------- tile loader: 2 x (128 rows x 128B), swizzled, via cp.async --------
#define STAGE_BYTES 32768
__device__ __forceinline__ void load_tiles(uint32_t ss, const uint4* Ah,
                                           const uint4* Bh, int kb, int tid) {
    #pragma unroll
    for (int l = 0; l < 4; l++) {
        int i = tid + l * 256;
        int row = i >> 3, ch = i & 7;
        uint32_t soff = (uint32_t)row * 128 + (uint32_t)((ch ^ (row & 7)) << 4);
        size_t goff = (size_t)row * 64 + (size_t)kb * 8 + ch;
        CP_A16(ss + soff,         Ah + goff);
        CP_A16(ss + 16384 + soff, Bh + goff);
    }
}

// -------- warp-tile compute: 32x64 per warp, 64 dims/stage, hi x hi only ----
__device__ __forceinline__ void compute_stage(uint32_t ss, int lane, int wm, int wn,
                                              float acc[2][8][4]) {
    uint32_t sAh = ss, sBh = ss + 16384;
    #pragma unroll
    for (int kk = 0; kk < 4; kk++) {
        uint32_t ah[2][4];
        #pragma unroll
        for (int i = 0; i < 2; i++) {
            int r = wm * 32 + i * 16 + (lane & 15);
            int c = (kk * 2 + (lane >> 4)) ^ (r & 7);
            ldsm4(ah[i], sAh + r * 128 + c * 16);
        }
        #pragma unroll
        for (int j16 = 0; j16 < 4; j16++) {
            int n = wn * 64 + j16 * 16 + (lane & 7) + ((lane >> 4) << 3);
            int c = (kk * 2 + ((lane >> 3) & 1)) ^ (n & 7);
            uint32_t bh[4];
            ldsm4(bh, sBh + n * 128 + c * 16);
            #pragma unroll
            for (int i = 0; i < 2; i++) {
                mma16816(acc[i][j16 * 2 + 0], ah[i], bh + 0);
                mma16816(acc[i][j16 * 2 + 1], ah[i], bh + 2);
            }
        }
    }
}

#define INS3(r, s, k) do {                                                        \
    if ((s) > v1[r]) { v3[r] = v2[r]; v2[r] = v1[r]; i2[r] = i1[r];               \
                       v1[r] = (s); i1[r] = (k); }                                \
    else if ((s) > v2[r]) { v3[r] = v2[r]; v2[r] = (s); i2[r] = (k); }            \
    else if ((s) > v3[r]) { v3[r] = (s); }                                        \
} while (0)

// -------- main dist + argmax/classify kernel --------
__global__ void __launch_bounds__(256, 2) vq_dist_kernel(float* __restrict__ out_ind_f) {
    extern __shared__ char smem[];
    uint32_t sb = smem_u32(smem);
    const int tid = threadIdx.x, lane = tid & 31, wid = tid >> 5;
    const int wm = wid & 3, wn = wid >> 2;
    const int m0 = blockIdx.x * 128;
    const uint4* Ah = (const uint4*)(g_Ah + (size_t)m0 * 256);

    float v1[4], v2[4], v3[4];
    int   i1[4], i2[4];
    #pragma unroll
    for (int r = 0; r < 4; r++) {
        v1[r] = v2[r] = v3[r] = -3.0e38f;
        i1[r] = i2[r] = 0;
    }

    for (int nt = 0; nt < 16; nt++) {
        const uint4* Bh = (const uint4*)(g_Bh + (size_t)nt * 128 * 256);

        float acc[2][8][4];
        #pragma unroll
        for (int i = 0; i < 2; i++)
            #pragma unroll
            for (int j = 0; j < 8; j++)
                #pragma unroll
                for (int q = 0; q < 4; q++) acc[i][j][q] = 0.f;

        load_tiles(sb, Ah, Bh, 0, tid);
        CP_COMMIT();
        for (int kb = 0; kb < 8; kb++) {
            uint32_t cur = sb + (kb & 1) * STAGE_BYTES;
            if (kb < 7) {
                load_tiles(sb + ((kb + 1) & 1) * STAGE_BYTES, Ah, Bh, kb + 1, tid);
                CP_COMMIT();
                CP_WAIT(1);
            } else {
                CP_WAIT(0);
            }
            __syncthreads();
            compute_stage(cur, lane, wm, wn, acc);
            __syncthreads();
        }

        #pragma unroll
        for (int j = 0; j < 8; j++) {
            int kb_ = nt * 128 + wn * 64 + j * 8 + (lane & 3) * 2;
            float e2a = g_e2[kb_], e2b = g_e2[kb_ + 1];
            #pragma unroll
            for (int i = 0; i < 2; i++) {
                float s0 = 2.f * acc[i][j][0] - e2a;
                float s1 = 2.f * acc[i][j][1] - e2b;
                float s2 = 2.f * acc[i][j][2] - e2a;
                float s3 = 2.f * acc[i][j][3] - e2b;
                int r0 = i * 2, r1 = i * 2 + 1;
                INS3(r0, s0, kb_);
                INS3(r0, s1, kb_ + 1);
                INS3(r1, s2, kb_);
                INS3(r1, s3, kb_ + 1);
            }
        }
    }

    // ---- per-row merge over 8 sources, classify row ----
    float* sV = (float*)smem;                   // [128][8][3]
    int*   sI = (int*)(smem + 128 * 8 * 3 * 4); // [128][8][2]
    __syncthreads();
    #pragma unroll
    for (int r = 0; r < 4; r++) {
        int row = wm * 32 + (r >> 1) * 16 + (r & 1) * 8 + (lane >> 2);
        int src = wn * 4 + (lane & 3);
        float* v = sV + (row * 8 + src) * 3;
        v[0] = v1[r]; v[1] = v2[r]; v[2] = v3[r];
        int* ii = sI + (row * 8 + src) * 2;
        ii[0] = i1[r]; ii[1] = i2[r];
    }
    __syncthreads();
    if (tid < 128) {
        float b1 = -3.0e38f; int bi1 = 0x7fffffff;
        #pragma unroll
        for (int s = 0; s < 8; s++) {
            float v = sV[(tid * 8 + s) * 3];
            int   i = sI[(tid * 8 + s) * 2];
            if (v > b1 || (v == b1 && i < bi1)) { b1 = v; bi1 = i; }
        }
        float thr = b1 - MARGIN;
        int cand[4]; int nc = 0; bool overflow = false;
        #pragma unroll
        for (int s = 0; s < 8; s++) {
            float va = sV[(tid * 8 + s) * 3 + 0];
            float vb = sV[(tid * 8 + s) * 3 + 1];
            float vc = sV[(tid * 8 + s) * 3 + 2];
            int ia = sI[(tid * 8 + s) * 2 + 0];
            int ib = sI[(tid * 8 + s) * 2 + 1];
            if (va >= thr) { if (nc < 4) cand[nc] = ia; nc++; }
            if (vb >= thr) { if (nc < 4) cand[nc] = ib; nc++; }
            if (vc >= thr) overflow = true;
        }
        int m = m0 + tid;
        if (!overflow && nc <= 1) {
            g_ind[m] = bi1;
            out_ind_f[m] = (float)bi1;
        } else if (!overflow && nc <= 4) {
            int slot = atomicAdd(&g_nlight, 1);
            g_lightm[slot] = m;
            #pragma unroll
            for (int c = 0; c < 4; c++) g_cand[(size_t)slot * 4 + c] = (c < nc) ? cand[c] : -1;
        } else {
            int slot = atomicAdd(&g_nfull, 1);
            g_fullm[slot] = m;
        }
    }
}

// -------- light fallback: exact rescore of <=4 candidates, WARP per row -----
__global__ __launch_bounds__(256) void light_kernel(const float* __restrict__ x,
                                                    const float* __restrict__ embed,
                                                    float* __restrict__ out_ind_f) {
    const int nl = g_nlight;
    const int lane = threadIdx.x & 31;
    const int wglob = blockIdx.x * 8 + (threadIdx.x >> 5);
    for (int s = wglob; s < nl; s += gridDim.x * 8) {
        int m = g_lightm[s];
        int b = m >> 13, n = m & (N_DIM - 1);
        const float* xb = x + (size_t)b * D_DIM * N_DIM + n;
        float xr[16];
        #pragma unroll
        for (int j = 0; j < 16; j++)
            xr[j] = xb[(size_t)(lane + 32 * j) * N_DIM];
        float best = -3.0e38f; int bi = 0x7fffffff;
        #pragma unroll
        for (int c = 0; c < 4; c++) {
            int k = g_cand[(size_t)s * 4 + c];
            if (k < 0) break;
            const float* e = embed + (size_t)k * D_DIM;
            float a = 0.f;
            #pragma unroll
            for (int j = 0; j < 16; j++)
                a += xr[j] * e[lane + 32 * j];
            #pragma unroll
            for (int o = 16; o > 0; o >>= 1)
                a += __shfl_xor_sync(0xffffffffu, a, o);
            float sc = 2.f * a - g_e2[k];
            if (sc > best || (sc == best && k < bi)) { best = sc; bi = k; }
        }
        if (lane == 0) { g_ind[m] = bi; out_ind_f[m] = (float)bi; }
    }
}

// -------- full fallback: exact scan of all codewords (rare) --------
__global__ __launch_bounds__(256) void full_kernel(const float* __restrict__ x,
                                                   const float* __restrict__ embed,
                                                   float* __restrict__ out_ind_f) {
    __shared__ float xr[D_DIM];
    __shared__ float bv[256];
    __shared__ int   bI[256];
    int nf = g_nfull;
    for (int f = blockIdx.x; f < nf; f += gridDim.x) {
        int m = g_fullm[f];
        int b = m >> 13, n = m & (N_DIM - 1);
        __syncthreads();
        for (int d = threadIdx.x; d < D_DIM; d += 256)
            xr[d] = x[(size_t)b * D_DIM * N_DIM + (size_t)d * N_DIM + n];
        __syncthreads();
        float best = -3.0e38f; int bi = 0x7fffffff;
        for (int c = 0; c < 8; c++) {
            int k = threadIdx.x + c * 256;
            const float4* er = (const float4*)(embed + (size_t)k * D_DIM);
            float s0 = 0.f, s1 = 0.f, s2 = 0.f, s3 = 0.f;
            #pragma unroll 8
            for (int j = 0; j < 128; j++) {
                float4 e = er[j];
                s0 += xr[4 * j + 0] * e.x;
                s1 += xr[4 * j + 1] * e.y;
                s2 += xr[4 * j + 2] * e.z;
                s3 += xr[4 * j + 3] * e.w;
            }
            float sc = 2.f * ((s0 + s1) + (s2 + s3)) - g_e2[k];
            if (sc > best || (sc == best && k < bi)) { best = sc; bi = k; }
        }
        bv[threadIdx.x] = best; bI[threadIdx.x] = bi;
        __syncthreads();
        for (int o = 128; o > 0; o >>= 1) {
            if (threadIdx.x < o) {
                float ov = bv[threadIdx.x + o]; int oi = bI[threadIdx.x + o];
                if (ov > bv[threadIdx.x] || (ov == bv[threadIdx.x] && oi < bI[threadIdx.x])) {
                    bv[threadIdx.x] = ov; bI[threadIdx.x] = oi;
                }
            }
            __syncthreads();
        }
        if (threadIdx.x == 0) { g_ind[m] = bI[0]; out_ind_f[m] = (float)bI[0]; }
    }
}

// -------- gather: out[b,d,n] = embed[ind[b,n], d] --------
__global__ __launch_bounds__(256) void gather_kernel(const float* __restrict__ embed,
                                                     float* __restrict__ out) {
    extern __shared__ float tile[];
    __shared__ int inds[32];
    const int bb = blockIdx.y;
    const int n0 = blockIdx.x * 32;
    if (threadIdx.x < 32) inds[threadIdx.x] = g_ind[bb * N_DIM + n0 + threadIdx.x];
    __syncthreads();
    for (int i = threadIdx.x; i < 32 * D_DIM; i += 256) {
        int n = i >> 9, d = i & (D_DIM - 1);
        tile[n * 513 + d] = embed[(size_t)inds[n] * D_DIM + d];
    }
    __syncthreads();
    float* obase = out + (size_t)bb * D_DIM * N_DIM + n0;
    for (int i = threadIdx.x; i < 32 * D_DIM; i += 256) {
        int n = i & 31, d = i >> 5;
        obase[(size_t)d * N_DIM + n] = tile[n * 513 + d];
    }
}

// ---------------------------------------------------------------------------
extern "C" void kernel_launch(void* const* d_in, const int* in_sizes, int n_in,
                              void* d_out, int out_size) {
    const float* x     = (const float*)d_in[0];
    const float* embed = (const float*)d_in[1];
    float* out   = (float*)d_out;
    float* out_q = out;
    float* out_i = out + (size_t)B_DIM * D_DIM * N_DIM;
    (void)in_sizes; (void)n_in; (void)out_size;

    static const int gather_smem = 32 * 513 * (int)sizeof(float);
    static const int dist_smem = 2 * STAGE_BYTES;   // 64 KB
    cudaFuncSetAttribute(gather_kernel, cudaFuncAttributeMaxDynamicSharedMemorySize, gather_smem);
    cudaFuncSetAttribute(vq_dist_kernel, cudaFuncAttributeMaxDynamicSharedMemorySize, dist_smem);

    prep_embed_kernel<<<K_CB, 128>>>(embed);
    prep_x_kernel<<<dim3(N_DIM / 64, B_DIM), 256>>>(x);
    vq_dist_kernel<<<M_ROWS / 128, 256, dist_smem>>>(out_i);
    light_kernel<<<1024, 256>>>(x, embed, out_i);
    full_kernel<<<128, 256>>>(x, embed, out_i);
    gather_kernel<<<dim3(N_DIM / 32, B_DIM), 256, gather_smem>>>(embed, out_q);
}